// round 2
// baseline (speedup 1.0000x reference)
#include <cuda_runtime.h>
#include <cuda_bf16.h>
#include <cstdint>

#define N_NODES 10000
#define N_EDGES 163840
#define IN_SIZE 512
#define H_SIZE 512
#define OUT_SIZE 64

// ---------------- scratch (device globals; no allocation allowed) ----------
__device__ float g_deg[N_NODES];
__device__ float g_dinv[N_NODES];
__device__ float g_h1[(size_t)N_NODES * H_SIZE];    // x@W1, later relu'd activations
__device__ float g_agg1[(size_t)N_NODES * H_SIZE];  // edge-aggregated layer1
__device__ float g_h2[(size_t)N_NODES * OUT_SIZE];  // y@W2
__device__ float g_agg2[(size_t)N_NODES * OUT_SIZE];

// ---------------- helpers ---------------------------------------------------
__device__ __forceinline__ void red_add_v4(float* addr, float4 v) {
    asm volatile("red.global.add.v4.f32 [%0], {%1,%2,%3,%4};"
                 :: "l"(addr), "f"(v.x), "f"(v.y), "f"(v.z), "f"(v.w)
                 : "memory");
}
__device__ __forceinline__ void red_add_v2(float* addr, float2 v) {
    asm volatile("red.global.add.v2.f32 [%0], {%1,%2};"
                 :: "l"(addr), "f"(v.x), "f"(v.y)
                 : "memory");
}

// ---------------- degree / norm ---------------------------------------------
__global__ void k_init(float* deg, float4* agg1, float4* agg2,
                       int n_agg1_v4, int n_agg2_v4) {
    int i = blockIdx.x * blockDim.x + threadIdx.x;
    int stride = gridDim.x * blockDim.x;
    for (int j = i; j < N_NODES; j += stride) deg[j] = 1.0f;  // self-loop
    float4 z = make_float4(0.f, 0.f, 0.f, 0.f);
    for (int j = i; j < n_agg1_v4; j += stride) agg1[j] = z;
    for (int j = i; j < n_agg2_v4; j += stride) agg2[j] = z;
}

__global__ void k_count_deg(const int* __restrict__ dst, float* deg) {
    int e = blockIdx.x * blockDim.x + threadIdx.x;
    if (e < N_EDGES) atomicAdd(&deg[dst[e]], 1.0f);
}

__global__ void k_dinv(const float* __restrict__ deg, float* dinv) {
    int i = blockIdx.x * blockDim.x + threadIdx.x;
    if (i < N_NODES) dinv[i] = rsqrtf(deg[i]);
}

// ---------------- SGEMM: C[M,N] = A[M,K] @ B[K,N], row-major ----------------
// (BM/TM)*(BN/TN) must equal 256 (thread count).
template <int BM, int BN, int BK, int TM, int TN>
__global__ __launch_bounds__(256, 2)
void k_sgemm(const float* __restrict__ A, const float* __restrict__ B,
             float* __restrict__ C, int M, int N, int K) {
    __shared__ float As[BK][BM + 4];
    __shared__ float Bs[BK][BN];

    const int tid = threadIdx.x;
    const int bm = blockIdx.x * BM;
    const int bn = blockIdx.y * BN;

    const int tm = (tid / (BN / TN)) * TM;
    const int tn = (tid % (BN / TN)) * TN;

    float acc[TM][TN];
#pragma unroll
    for (int m = 0; m < TM; m++)
#pragma unroll
        for (int n = 0; n < TN; n++) acc[m][n] = 0.f;

    constexpr int LA = (BM * BK) / (4 * 256);   // float4 loads of A per thread
    constexpr int LB = (BK * BN) / (4 * 256);   // float4 loads of B per thread

    for (int k0 = 0; k0 < K; k0 += BK) {
#pragma unroll
        for (int i = 0; i < LA; i++) {
            int idx = tid + i * 256;
            int row = idx / (BK / 4);
            int kc4 = (idx % (BK / 4)) * 4;
            float4 v = make_float4(0.f, 0.f, 0.f, 0.f);
            if (bm + row < M)
                v = *reinterpret_cast<const float4*>(&A[(size_t)(bm + row) * K + k0 + kc4]);
            As[kc4 + 0][row] = v.x;
            As[kc4 + 1][row] = v.y;
            As[kc4 + 2][row] = v.z;
            As[kc4 + 3][row] = v.w;
        }
#pragma unroll
        for (int i = 0; i < LB; i++) {
            int idx = tid + i * 256;
            int kr = idx / (BN / 4);
            int nc4 = (idx % (BN / 4)) * 4;
            *reinterpret_cast<float4*>(&Bs[kr][nc4]) =
                *reinterpret_cast<const float4*>(&B[(size_t)(k0 + kr) * N + bn + nc4]);
        }
        __syncthreads();

#pragma unroll
        for (int kk = 0; kk < BK; kk++) {
            float ra[TM], rb[TN];
#pragma unroll
            for (int m = 0; m < TM; m += 4)
                *reinterpret_cast<float4*>(&ra[m]) =
                    *reinterpret_cast<const float4*>(&As[kk][tm + m]);
#pragma unroll
            for (int n = 0; n < TN; n += 4)
                *reinterpret_cast<float4*>(&rb[n]) =
                    *reinterpret_cast<const float4*>(&Bs[kk][tn + n]);
#pragma unroll
            for (int m = 0; m < TM; m++)
#pragma unroll
                for (int n = 0; n < TN; n++) acc[m][n] += ra[m] * rb[n];
        }
        __syncthreads();
    }

#pragma unroll
    for (int m = 0; m < TM; m++) {
        int row = bm + tm + m;
        if (row < M) {
#pragma unroll
            for (int n = 0; n < TN; n += 4) {
                float4 v = make_float4(acc[m][n], acc[m][n + 1], acc[m][n + 2], acc[m][n + 3]);
                *reinterpret_cast<float4*>(&C[(size_t)row * N + bn + tn + n]) = v;
            }
        }
    }
}

// ---------------- scatter layer 1: agg1[dst] += h1[src] * norm (512 wide) ---
__global__ __launch_bounds__(256)
void k_scatter1(const int* __restrict__ src, const int* __restrict__ dst,
                const float* __restrict__ dinv, const float* __restrict__ h,
                float* agg) {
    int gt = blockIdx.x * blockDim.x + threadIdx.x;
    int e = gt >> 5;
    if (e >= N_EDGES) return;
    int lane = gt & 31;
    int s = __ldg(&src[e]);
    int d = __ldg(&dst[e]);
    float norm = __ldg(&dinv[s]) * __ldg(&dinv[d]);
    const float4* hp = reinterpret_cast<const float4*>(h + (size_t)s * H_SIZE);
    float* ap = agg + (size_t)d * H_SIZE;
#pragma unroll
    for (int i = 0; i < 4; i++) {
        int off = lane + i * 32;  // float4 index 0..127
        float4 v = __ldg(&hp[off]);
        v.x *= norm; v.y *= norm; v.z *= norm; v.w *= norm;
        red_add_v4(ap + (size_t)off * 4, v);
    }
}

// ---------------- finish layer 1: y = relu(agg1 + h1*dinv^2 + b1) -----------
__global__ void k_finish1(float* __restrict__ h1, const float* __restrict__ agg1,
                          const float* __restrict__ dinv, const float* __restrict__ b1) {
    int idx = blockIdx.x * blockDim.x + threadIdx.x;  // float4 index
    const int total = N_NODES * (H_SIZE / 4);
    if (idx >= total) return;
    int row = idx >> 7;          // /128 float4 per row
    int col4 = idx & 127;
    float di = dinv[row];
    float w = di * di;
    float4 a = reinterpret_cast<const float4*>(agg1)[idx];
    float4 hh = reinterpret_cast<float4*>(h1)[idx];
    float4 bb = reinterpret_cast<const float4*>(b1)[col4];
    float4 r;
    r.x = fmaxf(a.x + hh.x * w + bb.x, 0.f);
    r.y = fmaxf(a.y + hh.y * w + bb.y, 0.f);
    r.z = fmaxf(a.z + hh.z * w + bb.z, 0.f);
    r.w = fmaxf(a.w + hh.w * w + bb.w, 0.f);
    reinterpret_cast<float4*>(h1)[idx] = r;
}

// ---------------- scatter layer 2: agg2[dst] += h2[src] * norm (64 wide) ----
__global__ __launch_bounds__(256)
void k_scatter2(const int* __restrict__ src, const int* __restrict__ dst,
                const float* __restrict__ dinv, const float* __restrict__ h,
                float* agg) {
    int gt = blockIdx.x * blockDim.x + threadIdx.x;
    int e = gt >> 5;
    if (e >= N_EDGES) return;
    int lane = gt & 31;
    int s = __ldg(&src[e]);
    int d = __ldg(&dst[e]);
    float norm = __ldg(&dinv[s]) * __ldg(&dinv[d]);
    const float2* hp = reinterpret_cast<const float2*>(h + (size_t)s * OUT_SIZE);
    float* ap = agg + (size_t)d * OUT_SIZE;
    float2 v = __ldg(&hp[lane]);
    v.x *= norm; v.y *= norm;
    red_add_v2(ap + (size_t)lane * 2, v);
}

// ---------------- finish layer 2 + log_softmax, write both outputs ----------
__global__ __launch_bounds__(256)
void k_finish2(const float* __restrict__ agg2, const float* __restrict__ h2,
               const float* __restrict__ dinv, const float* __restrict__ b2,
               float* __restrict__ out) {
    int gt = blockIdx.x * blockDim.x + threadIdx.x;
    int node = gt >> 5;
    if (node >= N_NODES) return;
    int lane = gt & 31;
    float di = dinv[node];
    float w = di * di;
    size_t base = (size_t)node * OUT_SIZE;
    float v0 = agg2[base + lane]      + h2[base + lane]      * w + b2[lane];
    float v1 = agg2[base + lane + 32] + h2[base + lane + 32] * w + b2[lane + 32];
    out[base + lane] = v0;
    out[base + lane + 32] = v1;
    float m = fmaxf(v0, v1);
#pragma unroll
    for (int o = 16; o > 0; o >>= 1) m = fmaxf(m, __shfl_xor_sync(0xffffffffu, m, o));
    float s = expf(v0 - m) + expf(v1 - m);
#pragma unroll
    for (int o = 16; o > 0; o >>= 1) s += __shfl_xor_sync(0xffffffffu, s, o);
    float lse = m + logf(s);
    const size_t half = (size_t)N_NODES * OUT_SIZE;
    out[half + base + lane] = v0 - lse;
    out[half + base + lane + 32] = v1 - lse;
}

// ---------------- launch ----------------------------------------------------
extern "C" void kernel_launch(void* const* d_in, const int* in_sizes, int n_in,
                              void* d_out, int out_size) {
    const float* x  = (const float*)d_in[0];
    const int*   ei = (const int*)d_in[1];          // [2, E]: src then dst
    const float* W1 = (const float*)d_in[2];
    const float* b1 = (const float*)d_in[3];
    const float* W2 = (const float*)d_in[4];
    const float* b2 = (const float*)d_in[5];
    float* out = (float*)d_out;

    const int* src = ei;
    const int* dst = ei + N_EDGES;

    float *deg, *dinv, *h1, *agg1, *h2, *agg2;
    cudaGetSymbolAddress((void**)&deg,  g_deg);
    cudaGetSymbolAddress((void**)&dinv, g_dinv);
    cudaGetSymbolAddress((void**)&h1,   g_h1);
    cudaGetSymbolAddress((void**)&agg1, g_agg1);
    cudaGetSymbolAddress((void**)&h2,   g_h2);
    cudaGetSymbolAddress((void**)&agg2, g_agg2);

    // 1) init deg=1, zero aggregation buffers
    const int n_agg1_v4 = N_NODES * (H_SIZE / 4);
    const int n_agg2_v4 = N_NODES * (OUT_SIZE / 4);
    k_init<<<1024, 256>>>(deg, (float4*)agg1, (float4*)agg2, n_agg1_v4, n_agg2_v4);

    // 2) degree count + dinv
    k_count_deg<<<(N_EDGES + 255) / 256, 256>>>(dst, deg);
    k_dinv<<<(N_NODES + 255) / 256, 256>>>(deg, dinv);

    // 3) GEMM1: h1 = x @ W1   [10000,512] = [10000,512]x[512,512]
    {
        dim3 grid((N_NODES + 127) / 128, H_SIZE / 128);
        k_sgemm<128, 128, 16, 8, 8><<<grid, 256>>>(x, W1, h1, N_NODES, H_SIZE, IN_SIZE);
    }

    // 4) scatter layer 1 (edge aggregation)
    k_scatter1<<<(N_EDGES * 32 + 255) / 256, 256>>>(src, dst, dinv, h1, agg1);

    // 5) epilogue 1: y = relu(agg1 + h1*dinv^2 + b1)  (in place into h1)
    k_finish1<<<(N_NODES * (H_SIZE / 4) + 255) / 256, 256>>>(h1, agg1, dinv, b1);

    // 6) GEMM2: h2 = y @ W2   [10000,64] = [10000,512]x[512,64]
    {
        dim3 grid((N_NODES + 63) / 64, OUT_SIZE / 64);
        k_sgemm<64, 64, 16, 4, 4><<<grid, 256>>>(h1, W2, h2, N_NODES, OUT_SIZE, H_SIZE);
    }

    // 7) scatter layer 2
    k_scatter2<<<(N_EDGES * 32 + 255) / 256, 256>>>(src, dst, dinv, h2, agg2);

    // 8) epilogue 2 + log_softmax -> d_out [h ; log_softmax(h)]
    k_finish2<<<(N_NODES * 32 + 255) / 256, 256>>>(agg2, h2, dinv, b2, out);
}

// round 3
// speedup vs baseline: 1.6392x; 1.6392x over previous
#include <cuda_runtime.h>
#include <cuda_bf16.h>
#include <mma.h>
#include <cstdint>

using namespace nvcuda;

#define N_NODES 10000
#define N_EDGES 163840
#define IN_SIZE 512
#define H_SIZE 512
#define OUT_SIZE 64
#define M_PAD 10112   // padded row count (>= ceil(10000/128)*128)

// ---------------- scratch (device globals; no allocation allowed) ----------
__device__ float g_dinv[N_NODES];
__device__ int   g_cnt[N_NODES];
__device__ int   g_rowptr[N_NODES + 1];
__device__ int   g_cursor[N_NODES];
__device__ int   g_csrc[N_EDGES];
__device__ float g_h1[(size_t)M_PAD * H_SIZE];   // x@W1 (raw)
__device__ float g_y[(size_t)M_PAD * H_SIZE];    // relu(Â h1 + b1)
__device__ float g_h2[(size_t)M_PAD * OUT_SIZE]; // y@W2 (raw)

// ---------------- CSR build -------------------------------------------------
__global__ void k_zero_cnt(int* cnt) {
    int i = blockIdx.x * blockDim.x + threadIdx.x;
    if (i < N_NODES) cnt[i] = 0;
}

__global__ void k_hist(const int* __restrict__ dst, int* cnt) {
    int e = blockIdx.x * blockDim.x + threadIdx.x;
    if (e < N_EDGES) atomicAdd(&cnt[dst[e]], 1);
}

// single-block scan over 10000 counts -> rowptr (exclusive), cursor, dinv
#define SCAN_T 1024
#define SCAN_E 10
__global__ __launch_bounds__(SCAN_T)
void k_scan(const int* __restrict__ cnt, int* rowptr, int* cursor, float* dinv) {
    __shared__ int sums[SCAN_T];
    int t = threadIdx.x;
    int base = t * SCAN_E;
    int c[SCAN_E];
    int incl[SCAN_E];
    int s = 0;
#pragma unroll
    for (int i = 0; i < SCAN_E; i++) {
        int idx = base + i;
        c[i] = (idx < N_NODES) ? cnt[idx] : 0;
        s += c[i];
        incl[i] = s;
    }
    sums[t] = s;
    __syncthreads();
    // Hillis-Steele inclusive scan over 1024 partials
    for (int off = 1; off < SCAN_T; off <<= 1) {
        int v = (t >= off) ? sums[t - off] : 0;
        __syncthreads();
        sums[t] += v;
        __syncthreads();
    }
    int excl = (t == 0) ? 0 : sums[t - 1];
#pragma unroll
    for (int i = 0; i < SCAN_E; i++) {
        int idx = base + i;
        if (idx < N_NODES) {
            int start = excl + incl[i] - c[i];
            rowptr[idx] = start;
            cursor[idx] = start;
            dinv[idx] = rsqrtf((float)(c[i] + 1));  // +1 self loop
        }
    }
    if (t == SCAN_T - 1) rowptr[N_NODES] = sums[SCAN_T - 1];
}

__global__ void k_fill(const int* __restrict__ src, const int* __restrict__ dst,
                       int* cursor, int* csrc) {
    int e = blockIdx.x * blockDim.x + threadIdx.x;
    if (e >= N_EDGES) return;
    int d = dst[e];
    int pos = atomicAdd(&cursor[d], 1);
    csrc[pos] = src[e];
}

// ---------------- TF32 WMMA GEMM: C[M_pad,N] = A[M,K] @ B[K,N] --------------
// C rows are padded (stores unguarded); A rows >= M read as zero.
template <int BM, int BN, int BK, int WM, int WN>
__global__ __launch_bounds__(256)
void k_wmma(const float* __restrict__ A, const float* __restrict__ B,
            float* __restrict__ C, int M, int N, int K) {
    constexpr int LDA = BK + 4;
    constexpr int LDB = BN + 4;
    constexpr int WTM = BM / WM;
    constexpr int WTN = BN / WN;
    constexpr int FM = WTM / 16;
    constexpr int FN = WTN / 16;
    __shared__ float As[BM * LDA];
    __shared__ float Bs[BK * LDB];

    const int tid = threadIdx.x;
    const int wid = tid >> 5;
    const int wm = wid % WM;
    const int wn = wid / WM;
    const int bm = blockIdx.x * BM;
    const int bn = blockIdx.y * BN;

    wmma::fragment<wmma::accumulator, 16, 16, 8, float> acc[FM][FN];
#pragma unroll
    for (int fm = 0; fm < FM; fm++)
#pragma unroll
        for (int fn = 0; fn < FN; fn++) wmma::fill_fragment(acc[fm][fn], 0.0f);

    constexpr int LA = (BM * BK) / (4 * 256);
    constexpr int LB = (BK * BN) / (4 * 256);

    for (int k0 = 0; k0 < K; k0 += BK) {
#pragma unroll
        for (int i = 0; i < LA; i++) {
            int idx = tid + i * 256;
            int row = idx / (BK / 4);
            int c4 = (idx % (BK / 4)) * 4;
            float4 v = make_float4(0.f, 0.f, 0.f, 0.f);
            if (bm + row < M)
                v = *reinterpret_cast<const float4*>(&A[(size_t)(bm + row) * K + k0 + c4]);
            As[row * LDA + c4 + 0] = wmma::__float_to_tf32(v.x);
            As[row * LDA + c4 + 1] = wmma::__float_to_tf32(v.y);
            As[row * LDA + c4 + 2] = wmma::__float_to_tf32(v.z);
            As[row * LDA + c4 + 3] = wmma::__float_to_tf32(v.w);
        }
#pragma unroll
        for (int i = 0; i < LB; i++) {
            int idx = tid + i * 256;
            int kr = idx / (BN / 4);
            int c4 = (idx % (BN / 4)) * 4;
            float4 v = *reinterpret_cast<const float4*>(&B[(size_t)(k0 + kr) * N + bn + c4]);
            Bs[kr * LDB + c4 + 0] = wmma::__float_to_tf32(v.x);
            Bs[kr * LDB + c4 + 1] = wmma::__float_to_tf32(v.y);
            Bs[kr * LDB + c4 + 2] = wmma::__float_to_tf32(v.z);
            Bs[kr * LDB + c4 + 3] = wmma::__float_to_tf32(v.w);
        }
        __syncthreads();

#pragma unroll
        for (int kk = 0; kk < BK; kk += 8) {
            wmma::fragment<wmma::matrix_a, 16, 16, 8, wmma::precision::tf32, wmma::row_major> af[FM];
            wmma::fragment<wmma::matrix_b, 16, 16, 8, wmma::precision::tf32, wmma::row_major> bf[FN];
#pragma unroll
            for (int fm = 0; fm < FM; fm++)
                wmma::load_matrix_sync(af[fm], &As[(wm * WTM + fm * 16) * LDA + kk], LDA);
#pragma unroll
            for (int fn = 0; fn < FN; fn++)
                wmma::load_matrix_sync(bf[fn], &Bs[kk * LDB + wn * WTN + fn * 16], LDB);
#pragma unroll
            for (int fm = 0; fm < FM; fm++)
#pragma unroll
                for (int fn = 0; fn < FN; fn++)
                    wmma::mma_sync(acc[fm][fn], af[fm], bf[fn], acc[fm][fn]);
        }
        __syncthreads();
    }

#pragma unroll
    for (int fm = 0; fm < FM; fm++)
#pragma unroll
        for (int fn = 0; fn < FN; fn++)
            wmma::store_matrix_sync(
                &C[(size_t)(bm + wm * WTM + fm * 16) * N + bn + wn * WTN + fn * 16],
                acc[fm][fn], N, wmma::mem_row_major);
}

// ---------------- layer-1 aggregate (CSR gather) + self + bias + relu -------
__global__ __launch_bounds__(256)
void k_agg1(const int* __restrict__ rowptr, const int* __restrict__ csrc,
            const float* __restrict__ dinv, const float* __restrict__ h1,
            const float* __restrict__ b1, float* __restrict__ y) {
    int node = (blockIdx.x * blockDim.x + threadIdx.x) >> 5;
    if (node >= N_NODES) return;
    int lane = threadIdx.x & 31;
    int beg = __ldg(&rowptr[node]);
    int end = __ldg(&rowptr[node + 1]);
    float dd = __ldg(&dinv[node]);

    float4 a0 = {0, 0, 0, 0}, a1 = {0, 0, 0, 0}, a2 = {0, 0, 0, 0}, a3 = {0, 0, 0, 0};
    const float4* H = reinterpret_cast<const float4*>(h1);
    for (int j = beg; j < end; j++) {
        int s = __ldg(&csrc[j]);
        float nrm = dd * __ldg(&dinv[s]);
        const float4* hp = H + (size_t)s * 128;
        float4 v0 = __ldg(hp + lane);
        float4 v1 = __ldg(hp + lane + 32);
        float4 v2 = __ldg(hp + lane + 64);
        float4 v3 = __ldg(hp + lane + 96);
        a0.x += v0.x * nrm; a0.y += v0.y * nrm; a0.z += v0.z * nrm; a0.w += v0.w * nrm;
        a1.x += v1.x * nrm; a1.y += v1.y * nrm; a1.z += v1.z * nrm; a1.w += v1.w * nrm;
        a2.x += v2.x * nrm; a2.y += v2.y * nrm; a2.z += v2.z * nrm; a2.w += v2.w * nrm;
        a3.x += v3.x * nrm; a3.y += v3.y * nrm; a3.z += v3.z * nrm; a3.w += v3.w * nrm;
    }
    float w = dd * dd;
    const float4* hs = H + (size_t)node * 128;
    const float4* B4 = reinterpret_cast<const float4*>(b1);
    float4* Y = reinterpret_cast<float4*>(y) + (size_t)node * 128;
    float4 accs[4] = {a0, a1, a2, a3};
#pragma unroll
    for (int kchunk = 0; kchunk < 4; kchunk++) {
        int off = lane + kchunk * 32;
        float4 h = __ldg(hs + off);
        float4 b = __ldg(B4 + off);
        float4 r;
        r.x = fmaxf(accs[kchunk].x + h.x * w + b.x, 0.f);
        r.y = fmaxf(accs[kchunk].y + h.y * w + b.y, 0.f);
        r.z = fmaxf(accs[kchunk].z + h.z * w + b.z, 0.f);
        r.w = fmaxf(accs[kchunk].w + h.w * w + b.w, 0.f);
        Y[off] = r;
    }
}

// ---------------- layer-2 aggregate + self + bias + log_softmax -> out ------
__global__ __launch_bounds__(256)
void k_agg2(const int* __restrict__ rowptr, const int* __restrict__ csrc,
            const float* __restrict__ dinv, const float* __restrict__ h2,
            const float* __restrict__ b2, float* __restrict__ out) {
    int node = (blockIdx.x * blockDim.x + threadIdx.x) >> 5;
    if (node >= N_NODES) return;
    int lane = threadIdx.x & 31;
    int beg = __ldg(&rowptr[node]);
    int end = __ldg(&rowptr[node + 1]);
    float dd = __ldg(&dinv[node]);

    float2 acc = {0, 0};
    const float2* H2 = reinterpret_cast<const float2*>(h2);
    for (int j = beg; j < end; j++) {
        int s = __ldg(&csrc[j]);
        float nrm = dd * __ldg(&dinv[s]);
        float2 v = __ldg(H2 + (size_t)s * 32 + lane);
        acc.x += v.x * nrm;
        acc.y += v.y * nrm;
    }
    float w = dd * dd;
    float2 hv = __ldg(H2 + (size_t)node * 32 + lane);
    float2 bv = reinterpret_cast<const float2*>(b2)[lane];
    float v0 = acc.x + hv.x * w + bv.x;
    float v1 = acc.y + hv.y * w + bv.y;

    size_t base = (size_t)node * OUT_SIZE;
    out[base + 2 * lane] = v0;
    out[base + 2 * lane + 1] = v1;

    float m = fmaxf(v0, v1);
#pragma unroll
    for (int o = 16; o > 0; o >>= 1) m = fmaxf(m, __shfl_xor_sync(0xffffffffu, m, o));
    float s = expf(v0 - m) + expf(v1 - m);
#pragma unroll
    for (int o = 16; o > 0; o >>= 1) s += __shfl_xor_sync(0xffffffffu, s, o);
    float lse = m + logf(s);
    const size_t half = (size_t)N_NODES * OUT_SIZE;
    out[half + base + 2 * lane] = v0 - lse;
    out[half + base + 2 * lane + 1] = v1 - lse;
}

// ---------------- launch ----------------------------------------------------
extern "C" void kernel_launch(void* const* d_in, const int* in_sizes, int n_in,
                              void* d_out, int out_size) {
    const float* x  = (const float*)d_in[0];
    const int*   ei = (const int*)d_in[1];   // [2, E]: src row then dst row
    const float* W1 = (const float*)d_in[2];
    const float* b1 = (const float*)d_in[3];
    const float* W2 = (const float*)d_in[4];
    const float* b2 = (const float*)d_in[5];
    float* out = (float*)d_out;

    const int* src = ei;
    const int* dst = ei + N_EDGES;

    float *dinv, *h1, *y, *h2;
    int *cnt, *rowptr, *cursor, *csrc;
    cudaGetSymbolAddress((void**)&dinv,   g_dinv);
    cudaGetSymbolAddress((void**)&cnt,    g_cnt);
    cudaGetSymbolAddress((void**)&rowptr, g_rowptr);
    cudaGetSymbolAddress((void**)&cursor, g_cursor);
    cudaGetSymbolAddress((void**)&csrc,   g_csrc);
    cudaGetSymbolAddress((void**)&h1,     g_h1);
    cudaGetSymbolAddress((void**)&y,      g_y);
    cudaGetSymbolAddress((void**)&h2,     g_h2);

    // CSR build + norms
    k_zero_cnt<<<(N_NODES + 255) / 256, 256>>>(cnt);
    k_hist<<<(N_EDGES + 255) / 256, 256>>>(dst, cnt);
    k_scan<<<1, SCAN_T>>>(cnt, rowptr, cursor, dinv);
    k_fill<<<(N_EDGES + 255) / 256, 256>>>(src, dst, cursor, csrc);

    // GEMM1: h1 = x @ W1  (tf32 tensor cores)   [10000,512]x[512,512]
    {
        dim3 grid((N_NODES + 127) / 128, H_SIZE / 64);
        k_wmma<128, 64, 32, 4, 2><<<grid, 256>>>(x, W1, h1, N_NODES, H_SIZE, IN_SIZE);
    }

    // layer-1 aggregation + relu (CSR gather, fused epilogue)
    k_agg1<<<(N_NODES * 32 + 255) / 256, 256>>>(rowptr, csrc, dinv, h1, b1, y);

    // GEMM2: h2 = y @ W2   [10000,512]x[512,64]
    {
        dim3 grid((N_NODES + 63) / 64, OUT_SIZE / 64);
        k_wmma<64, 64, 32, 2, 4><<<grid, 256>>>(y, W2, h2, N_NODES, OUT_SIZE, H_SIZE);
    }

    // layer-2 aggregation + bias + log_softmax -> out
    k_agg2<<<(N_NODES * 32 + 255) / 256, 256>>>(rowptr, csrc, dinv, h2, b2, out);
}